// round 8
// baseline (speedup 1.0000x reference)
#include <cuda_runtime.h>
#include <math.h>
#include <stdint.h>

#define Bq 4
#define Sq 2048
#define Dq 1024
#define Mrows (Bq*Sq)   // 8192
#define GRU_BLOCKS 128
#define GRU_SMEM_BYTES ((24*264 + 4*264)*16 + 96*4)   // 118656

// ---------------- static device scratch (zero-initialized at load) ----------------
__device__ float g_ln [Mrows*Dq];          // ln1 out, then reused as GRU layer0 seq out
__device__ float g_xi [Mrows*3*Dq];        // GRU input-projection
__device__ float g_x1 [Mrows*Dq];          // x + gru
__device__ float g_mobA[Mrows*Dq];         // ln2 out / mobius ping
__device__ float g_mobB[Mrows*Dq];         // mobius pong / x2
__device__ float g_c1 [Mrows*Dq];
__device__ float g_c2 [Mrows*(Dq/2)];
__device__ float g_c3 [Mrows*(Dq/4)];
__device__ float g_tf [Mrows];
__device__ float g_ffn[Mrows*4*Dq];
__device__ float g_gc [Bq*Dq];
__device__ float g_gv [Bq];
__device__ float g_hbuf[2*Bq*Dq];          // GRU hidden-state ping-pong
__device__ int           g_bar_count;
__device__ volatile int  g_bar_sense;

// ---------------- helpers ----------------
__device__ __forceinline__ float gelu_f(float x) {
    return 0.5f * x * (1.0f + erff(x * 0.70710678118654752f));
}
__device__ __forceinline__ float sigmoid_f(float x) {
    return 1.0f / (1.0f + expf(-x));
}

// ---------------- LayerNorm: one block per row ----------------
__global__ void __launch_bounds__(256) ln_kernel(const float* __restrict__ x,
                                                 const float* __restrict__ gw,
                                                 const float* __restrict__ gb,
                                                 float* __restrict__ y)
{
    __shared__ float redA[8], redB[8];
    __shared__ float s_mean, s_rstd;
    int row = blockIdx.x, tid = threadIdx.x;
    const float4* xr = reinterpret_cast<const float4*>(x + (size_t)row*Dq);
    float4 v = xr[tid];
    float s = v.x+v.y+v.z+v.w;
    float q = v.x*v.x+v.y*v.y+v.z*v.z+v.w*v.w;
    #pragma unroll
    for (int o = 16; o > 0; o >>= 1) {
        s += __shfl_xor_sync(0xffffffffu, s, o);
        q += __shfl_xor_sync(0xffffffffu, q, o);
    }
    if ((tid & 31) == 0) { redA[tid>>5] = s; redB[tid>>5] = q; }
    __syncthreads();
    if (tid == 0) {
        float ss = 0.f, qq = 0.f;
        #pragma unroll
        for (int i = 0; i < 8; i++) { ss += redA[i]; qq += redB[i]; }
        float m = ss * (1.0f/1024.0f);
        float var = qq * (1.0f/1024.0f) - m*m;
        s_mean = m; s_rstd = rsqrtf(var + 1e-5f);
    }
    __syncthreads();
    float m = s_mean, r = s_rstd;
    const float4* g4 = reinterpret_cast<const float4*>(gw);
    const float4* b4 = reinterpret_cast<const float4*>(gb);
    float4 gv = g4[tid], bv = b4[tid], o;
    o.x = (v.x - m)*r*gv.x + bv.x;
    o.y = (v.y - m)*r*gv.y + bv.y;
    o.z = (v.z - m)*r*gv.z + bv.z;
    o.w = (v.w - m)*r*gv.w + bv.w;
    reinterpret_cast<float4*>(y + (size_t)row*Dq)[tid] = o;
}

// ---------------- SGEMM: C = act(A @ W^T + bias) (+ res) ----------------
// A: MxK row-major, W: NxK row-major. 128x128 tile, BK=8, 256 threads, 8x8 microtile.
template<int ACT, bool RES>
__global__ void __launch_bounds__(256) sgemm_kernel(
    const float* __restrict__ A, const float* __restrict__ W,
    const float* __restrict__ bias, const float* __restrict__ res,
    float* __restrict__ C, int M, int N, int K)
{
    __shared__ float As[8][128];
    __shared__ float Bs[8][128];
    int tid = threadIdx.x;
    int tx = tid & 15, ty = tid >> 4;
    int row0 = blockIdx.y * 128, col0 = blockIdx.x * 128;
    int lr = tid >> 1, lk = (tid & 1) * 4;
    const float* Ap = A + (size_t)(row0 + lr) * K + lk;
    const float* Wp = W + (size_t)(col0 + lr) * K + lk;
    float4 av = *(const float4*)Ap;
    float4 wv = *(const float4*)Wp;
    float acc[8][8];
    #pragma unroll
    for (int i = 0; i < 8; i++)
        #pragma unroll
        for (int j = 0; j < 8; j++) acc[i][j] = 0.f;

    for (int k0 = 0; k0 < K; k0 += 8) {
        __syncthreads();
        As[lk+0][lr]=av.x; As[lk+1][lr]=av.y; As[lk+2][lr]=av.z; As[lk+3][lr]=av.w;
        Bs[lk+0][lr]=wv.x; Bs[lk+1][lr]=wv.y; Bs[lk+2][lr]=wv.z; Bs[lk+3][lr]=wv.w;
        __syncthreads();
        if (k0 + 8 < K) {
            av = *(const float4*)(Ap + k0 + 8);
            wv = *(const float4*)(Wp + k0 + 8);
        }
        #pragma unroll
        for (int kk = 0; kk < 8; ++kk) {
            float4 a0 = *(const float4*)&As[kk][ty*4];
            float4 a1 = *(const float4*)&As[kk][64+ty*4];
            float4 b0 = *(const float4*)&Bs[kk][tx*4];
            float4 b1 = *(const float4*)&Bs[kk][64+tx*4];
            float a[8] = {a0.x,a0.y,a0.z,a0.w,a1.x,a1.y,a1.z,a1.w};
            float b[8] = {b0.x,b0.y,b0.z,b0.w,b1.x,b1.y,b1.z,b1.w};
            #pragma unroll
            for (int i = 0; i < 8; ++i)
                #pragma unroll
                for (int j = 0; j < 8; ++j)
                    acc[i][j] += a[i]*b[j];
        }
    }
    // epilogue
    #pragma unroll
    for (int i = 0; i < 8; ++i) {
        int r = row0 + ((i < 4) ? (ty*4 + i) : (64 + ty*4 + (i-4)));
        #pragma unroll
        for (int jj = 0; jj < 2; ++jj) {
            int cbase = col0 + (jj ? (64 + tx*4) : (tx*4));
            float vv[4];
            #pragma unroll
            for (int e = 0; e < 4; ++e) {
                float c = acc[i][jj*4+e] + __ldg(bias + cbase + e);
                if (ACT == 1) c = gelu_f(c);
                else if (ACT == 2) c = sigmoid_f(c);
                vv[e] = c;
            }
            if (RES) {
                float4 rv = *(const float4*)(res + (size_t)r*N + cbase);
                vv[0]+=rv.x; vv[1]+=rv.y; vv[2]+=rv.z; vv[3]+=rv.w;
            }
            float4 o; o.x=vv[0]; o.y=vv[1]; o.z=vv[2]; o.w=vv[3];
            *(float4*)(C + (size_t)r*N + cbase) = o;
        }
    }
}

// ---------------- persistent GRU layer ----------------
// xi: (B,S,3H) precomputed input projections; Whh: (3H,H); bhh: (3H)
// out: (B,S,H) = h_t sequence (+ res row if res != nullptr)
__global__ void __launch_bounds__(256,1) gru_kernel(
    const float* __restrict__ xi, const float* __restrict__ Whh,
    const float* __restrict__ bhh, const float* __restrict__ res,
    float* __restrict__ out)
{
    extern __shared__ float sm[];
    float4* Ws4 = reinterpret_cast<float4*>(sm);      // 24*264 float4 (swizzled)
    float4* hs4 = Ws4 + 24*264;                       // 4*264 float4 (swizzled)
    float*  hh_s = reinterpret_cast<float*>(hs4 + 4*264); // 96 floats
    const float* hsF = reinterpret_cast<const float*>(hs4);

    const int tid = threadIdx.x;
    const int u0  = blockIdx.x * 8;
    const int w   = tid >> 5, l = tid & 31;
    const int lb  = l & 3, lc = l >> 2;

    // Load this block's 24 W_hh rows into swizzled smem: slot(lr,c,k4)=lr*264+c*33+k4
    for (int s = tid; s < 24*256; s += 256) {
        int lr = s >> 8, rem = s & 255, c = rem >> 5, k4 = rem & 31;
        int g = lr >> 3, ui = lr & 7;
        const float4* src = reinterpret_cast<const float4*>(
            Whh + (size_t)(g*1024 + u0 + ui)*1024) + (c*32 + k4);
        Ws4[lr*264 + c*33 + k4] = __ldg(src);
    }
    float b_r = 0.f, b_z = 0.f, b_n = 0.f;
    const int p2i = tid >> 2, p2b = tid & 3;   // valid when tid < 32
    if (tid < 32) {
        b_r = __ldg(bhh + u0 + p2i);
        b_z = __ldg(bhh + 1024 + u0 + p2i);
        b_n = __ldg(bhh + 2048 + u0 + p2i);
    }
    __syncthreads();

    int local_sense = 0;
    for (int t = 0; t < Sq; ++t) {
        // stage h_{t-1} into smem (swizzled)
        if (t == 0) {
            float4 z4 = make_float4(0.f,0.f,0.f,0.f);
            for (int s = tid; s < 4*264; s += 256) hs4[s] = z4;
        } else {
            int rb = t & 1;
            #pragma unroll
            for (int i = 0; i < 4; ++i) {
                int s = tid*4 + i;                  // 0..1023
                int b = s >> 8, rem = s & 255, c = rem >> 5, k4 = rem & 31;
                const float4* gp = reinterpret_cast<const float4*>(
                    g_hbuf + rb*4096 + b*1024) + (c*32 + k4);
                hs4[b*264 + c*33 + k4] = __ldcg(const_cast<float4*>(gp));
            }
        }
        // prefetch xi (+res) for this step (independent of h)
        float xr=0.f, xz=0.f, xn=0.f, rv=0.f;
        if (tid < 32) {
            size_t rowb = (size_t)p2b*Sq + t;
            const float* xrow = xi + rowb*3072;
            xr = __ldg(xrow + u0 + p2i);
            xz = __ldg(xrow + 1024 + u0 + p2i);
            xn = __ldg(xrow + 2048 + u0 + p2i);
            if (res) rv = __ldg(res + rowb*1024 + u0 + p2i);
        }
        __syncthreads();

        // dot phase: warp w -> local rows 3w..3w+2, lane (lb=batch, lc=k-chunk)
        {
            float a0=0.f, a1=0.f, a2=0.f;
            int hb  = lb*264 + lc*33;
            int wb0 = (3*w+0)*264 + lc*33;
            int wb1 = (3*w+1)*264 + lc*33;
            int wb2 = (3*w+2)*264 + lc*33;
            #pragma unroll 8
            for (int k4 = 0; k4 < 32; ++k4) {
                float4 hv = hs4[hb + k4];
                float4 w0 = Ws4[wb0 + k4];
                a0 += hv.x*w0.x + hv.y*w0.y + hv.z*w0.z + hv.w*w0.w;
                float4 w1 = Ws4[wb1 + k4];
                a1 += hv.x*w1.x + hv.y*w1.y + hv.z*w1.z + hv.w*w1.w;
                float4 w2 = Ws4[wb2 + k4];
                a2 += hv.x*w2.x + hv.y*w2.y + hv.z*w2.z + hv.w*w2.w;
            }
            #pragma unroll
            for (int off = 4; off < 32; off <<= 1) {
                a0 += __shfl_xor_sync(0xffffffffu, a0, off);
                a1 += __shfl_xor_sync(0xffffffffu, a1, off);
                a2 += __shfl_xor_sync(0xffffffffu, a2, off);
            }
            if (lc == 0) {
                hh_s[(3*w+0)*4 + lb] = a0;
                hh_s[(3*w+1)*4 + lb] = a1;
                hh_s[(3*w+2)*4 + lb] = a2;
            }
        }
        __syncthreads();

        if (tid < 32) {
            float hr = hh_s[(0*8 + p2i)*4 + p2b] + b_r;
            float hz = hh_s[(1*8 + p2i)*4 + p2b] + b_z;
            float hn = hh_s[(2*8 + p2i)*4 + p2b] + b_n;
            int k = u0 + p2i;
            int c = k >> 7, k4 = (k & 127) >> 2, e = k & 3;
            float hprev = hsF[(p2b*264 + c*33 + k4)*4 + e];
            float rg = sigmoid_f(xr + hr);
            float zg = sigmoid_f(xz + hz);
            float ng = tanhf(xn + rg*hn);
            float hnew = (1.f - zg)*ng + zg*hprev;
            int wb = (t + 1) & 1;
            __stcg(g_hbuf + wb*4096 + p2b*1024 + k, hnew);
            out[((size_t)p2b*Sq + t)*1024 + k] = hnew + rv;
            __threadfence();
        }
        __syncthreads();

        // grid barrier (sense-reversing; even count per launch -> state returns to 0)
        local_sense ^= 1;
        if (tid == 0) {
            int arrived = atomicAdd(&g_bar_count, 1);
            if (arrived == (int)gridDim.x - 1) {
                g_bar_count = 0;
                __threadfence();
                g_bar_sense = local_sense;
            } else {
                while (g_bar_sense != local_sense) { }
                __threadfence();
            }
        }
        __syncthreads();
    }
}

// ---------------- gc = mean over S of ln2 output ----------------
__global__ void __launch_bounds__(256) gc_mean_kernel(const float* __restrict__ in,
                                                      float* __restrict__ gc)
{
    __shared__ float smv[256];
    int b = blockIdx.y, dchunk = blockIdx.x, tid = threadIdx.x;
    int d = dchunk*128 + (tid & 127);
    int half = tid >> 7;
    float acc = 0.f;
    const float* base = in + ((size_t)b*Sq + half*1024)*Dq + d;
    for (int s = 0; s < 1024; ++s) acc += base[(size_t)s*Dq];
    smv[tid] = acc;
    __syncthreads();
    if (tid < 128) gc[b*Dq + d] = (smv[tid] + smv[tid+128]) * (1.0f/2048.0f);
}

// ---------------- tiny global MLP: gc (4x1024) -> g scalar per batch ----------------
__global__ void __launch_bounds__(256) global_mlp_kernel(
    const float* __restrict__ gc,
    const float* __restrict__ gw1, const float* __restrict__ gb1,
    const float* __restrict__ gw2, const float* __restrict__ gb2,
    const float* __restrict__ gw3, const float* __restrict__ gb3,
    float* __restrict__ gv)
{
    __shared__ float xs[1024], h1[512], h2[256], red[8];
    int b = blockIdx.x, tid = threadIdx.x, w = tid >> 5, l = tid & 31;
    for (int i = tid; i < 1024; i += 256) xs[i] = gc[b*Dq + i];
    __syncthreads();
    for (int o = w*64; o < w*64 + 64; ++o) {
        const float* wr = gw1 + (size_t)o*1024;
        float acc = 0.f;
        for (int k = l; k < 1024; k += 32) acc += xs[k]*__ldg(wr + k);
        #pragma unroll
        for (int off = 16; off; off >>= 1) acc += __shfl_xor_sync(0xffffffffu, acc, off);
        if (l == 0) h1[o] = gelu_f(acc + __ldg(gb1 + o));
    }
    __syncthreads();
    for (int o = w*32; o < w*32 + 32; ++o) {
        const float* wr = gw2 + (size_t)o*512;
        float acc = 0.f;
        for (int k = l; k < 512; k += 32) acc += h1[k]*__ldg(wr + k);
        #pragma unroll
        for (int off = 16; off; off >>= 1) acc += __shfl_xor_sync(0xffffffffu, acc, off);
        if (l == 0) h2[o] = gelu_f(acc + __ldg(gb2 + o));
    }
    __syncthreads();
    float acc = h2[tid & 255] * __ldg(gw3 + (tid & 255));
    #pragma unroll
    for (int off = 16; off; off >>= 1) acc += __shfl_xor_sync(0xffffffffu, acc, off);
    if (l == 0) red[w] = acc;
    __syncthreads();
    if (tid == 0) {
        float s = 0.f;
        #pragma unroll
        for (int i = 0; i < 8; i++) s += red[i];
        gv[b] = sigmoid_f(s + __ldg(gb3));
    }
}

// ---------------- tf head: sigmoid(c3 @ cw4^T + cb4), one warp per row ----------------
__global__ void __launch_bounds__(256) tf_head_kernel(const float* __restrict__ c3,
                                                      const float* __restrict__ w4,
                                                      const float* __restrict__ b4,
                                                      float* __restrict__ tf)
{
    int tid = threadIdx.x, w = tid >> 5, l = tid & 31;
    int row = blockIdx.x*8 + w;
    const float* cr = c3 + (size_t)row*256;
    float acc = 0.f;
    #pragma unroll
    for (int k = l; k < 256; k += 32) acc += cr[k]*__ldg(w4 + k);
    #pragma unroll
    for (int off = 16; off; off >>= 1) acc += __shfl_xor_sync(0xffffffffu, acc, off);
    if (l == 0) tf[row] = sigmoid_f(acc + __ldg(b4));
}

// ---------------- mobius twist update: out = [res +] in + coup*twist(in) ----------------
template<bool ADDRES>
__global__ void __launch_bounds__(256) mobius_kernel(
    const float* __restrict__ in, const float* __restrict__ tf,
    const float* __restrict__ gv, const float* __restrict__ ar,
    const float* __restrict__ res, float* __restrict__ outp)
{
    int row = blockIdx.x, tid = threadIdx.x;
    int b = row >> 11;
    float coup = 0.1f + __ldg(ar)*((0.7f*__ldg(gv + b) + 0.3f*__ldg(tf + row)) - 0.5f)*2.0f;
    const float4* ir = reinterpret_cast<const float4*>(in + (size_t)row*Dq);
    int j = tid*4;
    float sign = (j < 256 || j >= 768) ? 1.f : -1.f;
    int src4 = tid + ((j < 512) ? 128 : -128);
    float4 xv = ir[tid], tv = ir[src4];
    float cs = coup*sign;
    float4 o;
    o.x = xv.x + cs*tv.x; o.y = xv.y + cs*tv.y;
    o.z = xv.z + cs*tv.z; o.w = xv.w + cs*tv.w;
    if (ADDRES) {
        float4 rv = reinterpret_cast<const float4*>(res + (size_t)row*Dq)[tid];
        o.x += rv.x; o.y += rv.y; o.z += rv.z; o.w += rv.w;
    }
    reinterpret_cast<float4*>(outp + (size_t)row*Dq)[tid] = o;
}

// ---------------- host driver ----------------
static float* symaddr(const void* sym) {
    void* p = nullptr;
    cudaGetSymbolAddress(&p, sym);
    return (float*)p;
}

extern "C" void kernel_launch(void* const* d_in, const int* in_sizes, int n_in,
                              void* d_out, int out_size) {
    const float* x     = (const float*)d_in[0];
    const float* g1w   = (const float*)d_in[1];
    const float* g1b   = (const float*)d_in[2];
    const float* g2w   = (const float*)d_in[3];
    const float* g2b   = (const float*)d_in[4];
    const float* W_ih0 = (const float*)d_in[5];
    const float* W_hh0 = (const float*)d_in[6];
    const float* b_ih0 = (const float*)d_in[7];
    const float* b_hh0 = (const float*)d_in[8];
    const float* W_ih1 = (const float*)d_in[9];
    const float* W_hh1 = (const float*)d_in[10];
    const float* b_ih1 = (const float*)d_in[11];
    const float* b_hh1 = (const float*)d_in[12];
    const float* cw1   = (const float*)d_in[13];
    const float* cb1   = (const float*)d_in[14];
    const float* cw2   = (const float*)d_in[15];
    const float* cb2   = (const float*)d_in[16];
    const float* cw3   = (const float*)d_in[17];
    const float* cb3   = (const float*)d_in[18];
    const float* cw4   = (const float*)d_in[19];
    const float* cb4   = (const float*)d_in[20];
    const float* gw1   = (const float*)d_in[21];
    const float* gb1   = (const float*)d_in[22];
    const float* gw2   = (const float*)d_in[23];
    const float* gb2   = (const float*)d_in[24];
    const float* gw3   = (const float*)d_in[25];
    const float* gb3   = (const float*)d_in[26];
    const float* arng  = (const float*)d_in[27];
    const float* fw1   = (const float*)d_in[28];
    const float* fb1   = (const float*)d_in[29];
    const float* fw2   = (const float*)d_in[30];
    const float* fb2   = (const float*)d_in[31];
    float* out = (float*)d_out;

    float* p_ln   = symaddr(g_ln);
    float* p_xi   = symaddr(g_xi);
    float* p_x1   = symaddr(g_x1);
    float* p_mobA = symaddr(g_mobA);
    float* p_mobB = symaddr(g_mobB);
    float* p_c1   = symaddr(g_c1);
    float* p_c2   = symaddr(g_c2);
    float* p_c3   = symaddr(g_c3);
    float* p_tf   = symaddr(g_tf);
    float* p_ffn  = symaddr(g_ffn);
    float* p_gc   = symaddr(g_gc);
    float* p_gv   = symaddr(g_gv);

    cudaFuncSetAttribute(gru_kernel, cudaFuncAttributeMaxDynamicSharedMemorySize,
                         GRU_SMEM_BYTES);

    // Block 1: ln1 -> GRU0 -> GRU1 -> + x
    ln_kernel<<<Mrows, 256>>>(x, g1w, g1b, p_ln);
    sgemm_kernel<0,false><<<dim3(3072/128, Mrows/128), 256>>>(
        p_ln, W_ih0, b_ih0, nullptr, p_xi, Mrows, 3072, 1024);
    gru_kernel<<<GRU_BLOCKS, 256, GRU_SMEM_BYTES>>>(p_xi, W_hh0, b_hh0, nullptr, p_ln);
    sgemm_kernel<0,false><<<dim3(3072/128, Mrows/128), 256>>>(
        p_ln, W_ih1, b_ih1, nullptr, p_xi, Mrows, 3072, 1024);
    gru_kernel<<<GRU_BLOCKS, 256, GRU_SMEM_BYTES>>>(p_xi, W_hh1, b_hh1, x, p_x1);

    // Block 2: ln2 -> adaptive mobius -> + x1
    ln_kernel<<<Mrows, 256>>>(p_x1, g2w, g2b, p_mobA);
    gc_mean_kernel<<<dim3(8, 4), 256>>>(p_mobA, p_gc);
    global_mlp_kernel<<<4, 256>>>(p_gc, gw1, gb1, gw2, gb2, gw3, gb3, p_gv);

    float* cin = p_mobA;
    float* cout = p_mobB;
    for (int cyc = 0; cyc < 3; ++cyc) {
        sgemm_kernel<1,false><<<dim3(1024/128, Mrows/128), 256>>>(
            cin, cw1, cb1, nullptr, p_c1, Mrows, 1024, 1024);
        sgemm_kernel<1,false><<<dim3(512/128, Mrows/128), 256>>>(
            p_c1, cw2, cb2, nullptr, p_c2, Mrows, 512, 1024);
        sgemm_kernel<1,false><<<dim3(256/128, Mrows/128), 256>>>(
            p_c2, cw3, cb3, nullptr, p_c3, Mrows, 256, 512);
        tf_head_kernel<<<Mrows/8, 256>>>(p_c3, cw4, cb4, p_tf);
        if (cyc == 2) {
            mobius_kernel<true><<<Mrows, 256>>>(cin, p_tf, p_gv, arng, p_x1, cout);
        } else {
            mobius_kernel<false><<<Mrows, 256>>>(cin, p_tf, p_gv, arng, nullptr, cout);
        }
        float* tmp = cin; cin = cout; cout = tmp;
    }
    // after 3 cycles (A->B, B->A, A->B), x2 lives in p_mobB
    float* p_x2 = p_mobB;

    // Block 3: FFN residual
    sgemm_kernel<1,false><<<dim3(4096/128, Mrows/128), 256>>>(
        p_x2, fw1, fb1, nullptr, p_ffn, Mrows, 4096, 1024);
    sgemm_kernel<0,true><<<dim3(1024/128, Mrows/128), 256>>>(
        p_ffn, fw2, fb2, p_x2, out, Mrows, 1024, 4096);

    (void)in_sizes; (void)n_in; (void)out_size;
}

// round 15
// speedup vs baseline: 1.1715x; 1.1715x over previous
#include <cuda_runtime.h>
#include <math.h>
#include <stdint.h>

#define Bq 4
#define Sq 2048
#define Dq 1024
#define Mrows (Bq*Sq)   // 8192
#define GRU_BLOCKS 128
#define GRU_SMEM_BYTES ((24*264 + 4*264)*16 + 96*4)   // 118656

// ---------------- static device scratch (zero-initialized at load) ----------------
__device__ float g_ln [Mrows*Dq];
__device__ float g_xi [Mrows*3*Dq];
__device__ float g_x1 [Mrows*Dq];
__device__ float g_mobA[Mrows*Dq];
__device__ float g_mobB[Mrows*Dq];
__device__ float g_c1 [Mrows*Dq];
__device__ float g_c2 [Mrows*(Dq/2)];
__device__ float g_c3 [Mrows*(Dq/4)];
__device__ float g_tf [Mrows];
__device__ float g_ffn[Mrows*4*Dq];
__device__ float g_gc [Bq*Dq];
__device__ float g_gv [Bq];
__device__ float g_hbuf[2*Bq*Dq];
__device__ int           g_bar_count;   // proven-good R7 barrier state
__device__ volatile int  g_bar_sense;

// ---------------- helpers ----------------
__device__ __forceinline__ float gelu_f(float x) {
    return 0.5f * x * (1.0f + erff(x * 0.70710678118654752f));
}
__device__ __forceinline__ float sigmoid_f(float x) {
    return 1.0f / (1.0f + expf(-x));
}
__device__ __forceinline__ uint32_t f2tf32(float f) {
    uint32_t u;
    asm("cvt.rna.tf32.f32 %0, %1;" : "=r"(u) : "f"(f));
    return u;
}
__device__ __forceinline__ void mma8(float* d, const uint32_t* a, const uint32_t* b) {
    asm volatile(
        "mma.sync.aligned.m16n8k8.row.col.f32.tf32.tf32.f32 "
        "{%0,%1,%2,%3}, {%4,%5,%6,%7}, {%8,%9}, {%0,%1,%2,%3};"
        : "+f"(d[0]), "+f"(d[1]), "+f"(d[2]), "+f"(d[3])
        : "r"(a[0]), "r"(a[1]), "r"(a[2]), "r"(a[3]), "r"(b[0]), "r"(b[1]));
}

// ---------------- LayerNorm: one block per row ----------------
__global__ void __launch_bounds__(256) ln_kernel(const float* __restrict__ x,
                                                 const float* __restrict__ gw,
                                                 const float* __restrict__ gb,
                                                 float* __restrict__ y)
{
    __shared__ float redA[8], redB[8];
    __shared__ float s_mean, s_rstd;
    int row = blockIdx.x, tid = threadIdx.x;
    const float4* xr = reinterpret_cast<const float4*>(x + (size_t)row*Dq);
    float4 v = xr[tid];
    float s = v.x+v.y+v.z+v.w;
    float q = v.x*v.x+v.y*v.y+v.z*v.z+v.w*v.w;
    #pragma unroll
    for (int o = 16; o > 0; o >>= 1) {
        s += __shfl_xor_sync(0xffffffffu, s, o);
        q += __shfl_xor_sync(0xffffffffu, q, o);
    }
    if ((tid & 31) == 0) { redA[tid>>5] = s; redB[tid>>5] = q; }
    __syncthreads();
    if (tid == 0) {
        float ss = 0.f, qq = 0.f;
        #pragma unroll
        for (int i = 0; i < 8; i++) { ss += redA[i]; qq += redB[i]; }
        float m = ss * (1.0f/1024.0f);
        float var = qq * (1.0f/1024.0f) - m*m;
        s_mean = m; s_rstd = rsqrtf(var + 1e-5f);
    }
    __syncthreads();
    float m = s_mean, r = s_rstd;
    const float4* g4 = reinterpret_cast<const float4*>(gw);
    const float4* b4 = reinterpret_cast<const float4*>(gb);
    float4 gv = g4[tid], bv = b4[tid], o;
    o.x = (v.x - m)*r*gv.x + bv.x;
    o.y = (v.y - m)*r*gv.y + bv.y;
    o.z = (v.z - m)*r*gv.z + bv.z;
    o.w = (v.w - m)*r*gv.w + bv.w;
    reinterpret_cast<float4*>(y + (size_t)row*Dq)[tid] = o;
}

// ---------------- tf32 tensor-core GEMM ----------------
// C[M,N] = act(A[M,K] @ W[N,K]^T + bias) (+ res). 128x128x32 tile, 256 thr.
// Warp grid 2(m) x 4(n); each warp: 64x32 via 4x4 mma m16n8k8 tiles.
// Smem stride 36 floats -> all fragment LDS conflict-free.
template<int ACT, bool RES>
__global__ void __launch_bounds__(256) tgemm_kernel(
    const float* __restrict__ A, const float* __restrict__ W,
    const float* __restrict__ bias, const float* __restrict__ res,
    float* __restrict__ C, int M, int N, int K)
{
    __shared__ uint32_t As[128*36];
    __shared__ uint32_t Ws[128*36];
    const int tid = threadIdx.x;
    const int lane = tid & 31, wid = tid >> 5;
    const int g = lane >> 2, tig = lane & 3;
    const int wm = wid >> 2, wn = wid & 3;
    const int row0 = blockIdx.y * 128, col0 = blockIdx.x * 128;
    const int Kq = K >> 2;

    float acc[4][4][4];
    #pragma unroll
    for (int i = 0; i < 4; i++)
        #pragma unroll
        for (int j = 0; j < 4; j++)
            #pragma unroll
            for (int e = 0; e < 4; e++) acc[i][j][e] = 0.f;

    const float4* Ag = reinterpret_cast<const float4*>(A) + (size_t)row0 * Kq;
    const float4* Wg = reinterpret_cast<const float4*>(W) + (size_t)col0 * Kq;

    int fm[4], fq[4];
    #pragma unroll
    for (int i = 0; i < 4; i++) { int f = tid + i*256; fm[i] = f >> 3; fq[i] = f & 7; }

    float4 pa[4], pw[4];
    #pragma unroll
    for (int i = 0; i < 4; i++) {
        pa[i] = Ag[(size_t)fm[i]*Kq + fq[i]];
        pw[i] = Wg[(size_t)fm[i]*Kq + fq[i]];
    }

    for (int k0 = 0; k0 < K; k0 += 32) {
        __syncthreads();
        #pragma unroll
        for (int i = 0; i < 4; i++) {
            uint4 ua, uw;
            ua.x = f2tf32(pa[i].x); ua.y = f2tf32(pa[i].y);
            ua.z = f2tf32(pa[i].z); ua.w = f2tf32(pa[i].w);
            uw.x = f2tf32(pw[i].x); uw.y = f2tf32(pw[i].y);
            uw.z = f2tf32(pw[i].z); uw.w = f2tf32(pw[i].w);
            *reinterpret_cast<uint4*>(&As[fm[i]*36 + fq[i]*4]) = ua;
            *reinterpret_cast<uint4*>(&Ws[fm[i]*36 + fq[i]*4]) = uw;
        }
        __syncthreads();
        if (k0 + 32 < K) {
            int kb4 = (k0 + 32) >> 2;
            #pragma unroll
            for (int i = 0; i < 4; i++) {
                pa[i] = Ag[(size_t)fm[i]*Kq + kb4 + fq[i]];
                pw[i] = Wg[(size_t)fm[i]*Kq + kb4 + fq[i]];
            }
        }
        #pragma unroll
        for (int ks = 0; ks < 4; ++ks) {
            int kb = ks * 8;
            uint32_t af[4][4];
            #pragma unroll
            for (int mt = 0; mt < 4; ++mt) {
                int mr = wm*64 + mt*16;
                af[mt][0] = As[(mr + g    )*36 + kb + tig    ];
                af[mt][1] = As[(mr + g + 8)*36 + kb + tig    ];
                af[mt][2] = As[(mr + g    )*36 + kb + tig + 4];
                af[mt][3] = As[(mr + g + 8)*36 + kb + tig + 4];
            }
            uint32_t bf[4][2];
            #pragma unroll
            for (int nt = 0; nt < 4; ++nt) {
                int nc = wn*32 + nt*8;
                bf[nt][0] = Ws[(nc + g)*36 + kb + tig    ];
                bf[nt][1] = Ws[(nc + g)*36 + kb + tig + 4];
            }
            #pragma unroll
            for (int mt = 0; mt < 4; ++mt)
                #pragma unroll
                for (int nt = 0; nt < 4; ++nt)
                    mma8(acc[mt][nt], af[mt], bf[nt]);
        }
    }

    // epilogue: c0=(g,2t) c1=(g,2t+1) c2=(g+8,2t) c3=(g+8,2t+1)
    #pragma unroll
    for (int mt = 0; mt < 4; ++mt) {
        #pragma unroll
        for (int nt = 0; nt < 4; ++nt) {
            int ra = row0 + wm*64 + mt*16 + g;
            int cc = col0 + wn*32 + nt*8 + 2*tig;
            float b0 = __ldg(bias + cc), b1 = __ldg(bias + cc + 1);
            #pragma unroll
            for (int h = 0; h < 2; ++h) {
                int r = ra + h*8;
                float v0 = acc[mt][nt][h*2+0] + b0;
                float v1 = acc[mt][nt][h*2+1] + b1;
                if (ACT == 1) { v0 = gelu_f(v0); v1 = gelu_f(v1); }
                else if (ACT == 2) { v0 = sigmoid_f(v0); v1 = sigmoid_f(v1); }
                if (RES) {
                    float2 rv = *reinterpret_cast<const float2*>(res + (size_t)r*N + cc);
                    v0 += rv.x; v1 += rv.y;
                }
                float2 o; o.x = v0; o.y = v1;
                *reinterpret_cast<float2*>(C + (size_t)r*N + cc) = o;
            }
        }
    }
}

// ---------------- persistent GRU layer (R7 proven atomic sense-reversing barrier) ----------------
__global__ void __launch_bounds__(256,1) gru_kernel(
    const float* __restrict__ xi, const float* __restrict__ Whh,
    const float* __restrict__ bhh, const float* __restrict__ res,
    float* __restrict__ out)
{
    extern __shared__ float sm[];
    float4* Ws4 = reinterpret_cast<float4*>(sm);          // 24*264 float4 (swizzled)
    float4* hs4 = Ws4 + 24*264;                           // 4*264 float4 (swizzled)
    float*  hh_s = reinterpret_cast<float*>(hs4 + 4*264); // 96 floats
    const float* hsF = reinterpret_cast<const float*>(hs4);

    const int tid = threadIdx.x;
    const int u0  = blockIdx.x * 8;
    const int w   = tid >> 5, l = tid & 31;
    const int lb  = l & 3, lc = l >> 2;

    // load 24 W_hh rows into swizzled smem: slot(lr,c,k4)=lr*264+c*33+k4
    for (int s = tid; s < 24*256; s += 256) {
        int lr = s >> 8, rem = s & 255, c = rem >> 5, k4 = rem & 31;
        int gg = lr >> 3, ui = lr & 7;
        const float4* src = reinterpret_cast<const float4*>(
            Whh + (size_t)(gg*1024 + u0 + ui)*1024) + (c*32 + k4);
        Ws4[lr*264 + c*33 + k4] = __ldg(src);
    }
    float b_r = 0.f, b_z = 0.f, b_n = 0.f;
    const int p2i = tid >> 2, p2b = tid & 3;   // valid when tid < 32
    if (tid < 32) {
        b_r = __ldg(bhh + u0 + p2i);
        b_z = __ldg(bhh + 1024 + u0 + p2i);
        b_n = __ldg(bhh + 2048 + u0 + p2i);
    }
    __syncthreads();

    int local_sense = 0;
    for (int t = 0; t < Sq; ++t) {
        // stage h_{t-1} into swizzled smem
        if (t == 0) {
            float4 z4 = make_float4(0.f,0.f,0.f,0.f);
            for (int s = tid; s < 4*264; s += 256) hs4[s] = z4;
        } else {
            int rb = t & 1;
            #pragma unroll
            for (int i = 0; i < 4; ++i) {
                int s = tid*4 + i;
                int b = s >> 8, rem = s & 255, c = rem >> 5, k4 = rem & 31;
                const float4* gp = reinterpret_cast<const float4*>(
                    g_hbuf + rb*4096 + b*1024) + (c*32 + k4);
                hs4[b*264 + c*33 + k4] = __ldcg(gp);
            }
        }
        float xr=0.f, xz=0.f, xn=0.f, rv=0.f;
        if (tid < 32) {
            size_t rowb = (size_t)p2b*Sq + t;
            const float* xrow = xi + rowb*3072;
            xr = __ldg(xrow + u0 + p2i);
            xz = __ldg(xrow + 1024 + u0 + p2i);
            xn = __ldg(xrow + 2048 + u0 + p2i);
            if (res) rv = __ldg(res + rowb*1024 + u0 + p2i);
        }
        __syncthreads();

        // dot phase: warp w -> rows 3w..3w+2; lanes (lb=batch, lc=k-chunk)
        {
            float a0=0.f, a1=0.f, a2=0.f;
            int hb  = lb*264 + lc*33;
            int wb0 = (3*w+0)*264 + lc*33;
            int wb1 = (3*w+1)*264 + lc*33;
            int wb2 = (3*w+2)*264 + lc*33;
            #pragma unroll 8
            for (int k4 = 0; k4 < 32; ++k4) {
                float4 hv = hs4[hb + k4];
                float4 w0 = Ws4[wb0 + k4];
                a0 += hv.x*w0.x + hv.y*w0.y + hv.z*w0.z + hv.w*w0.w;
                float4 w1 = Ws4[wb1 + k4];
                a1 += hv.x*w1.x + hv.y*w1.y + hv.z*w1.z + hv.w*w1.w;
                float4 w2 = Ws4[wb2 + k4];
                a2 += hv.x*w2.x + hv.y*w2.y + hv.z*w2.z + hv.w*w2.w;
            }
            #pragma unroll
            for (int off = 4; off < 32; off <<= 1) {
                a0 += __shfl_xor_sync(0xffffffffu, a0, off);
                a1 += __shfl_xor_sync(0xffffffffu, a1, off);
                a2 += __shfl_xor_sync(0xffffffffu, a2, off);
            }
            if (lc == 0) {
                hh_s[(3*w+0)*4 + lb] = a0;
                hh_s[(3*w+1)*4 + lb] = a1;
                hh_s[(3*w+2)*4 + lb] = a2;
            }
        }
        __syncthreads();

        if (tid < 32) {
            float hr = hh_s[(0*8 + p2i)*4 + p2b] + b_r;
            float hz = hh_s[(1*8 + p2i)*4 + p2b] + b_z;
            float hn = hh_s[(2*8 + p2i)*4 + p2b] + b_n;
            int k = u0 + p2i;
            int c = k >> 7, k4 = (k & 127) >> 2, e = k & 3;
            float hprev = hsF[(p2b*264 + c*33 + k4)*4 + e];
            float rg = sigmoid_f(xr + hr);
            float zg = sigmoid_f(xz + hz);
            float ng = tanhf(xn + rg*hn);
            float hnew = (1.f - zg)*ng + zg*hprev;
            int wb = (t + 1) & 1;
            __stcg(g_hbuf + wb*4096 + p2b*1024 + k, hnew);
            out[((size_t)p2b*Sq + t)*1024 + k] = hnew + rv;
            __threadfence();
        }
        __syncthreads();

        // grid barrier (R7 proven: atomic count + volatile sense; even count per
        // launch so state returns to 0 -> graph-replay safe)
        local_sense ^= 1;
        if (tid == 0) {
            int arrived = atomicAdd(&g_bar_count, 1);
            if (arrived == (int)gridDim.x - 1) {
                g_bar_count = 0;
                __threadfence();
                g_bar_sense = local_sense;
            } else {
                while (g_bar_sense != local_sense) { }
                __threadfence();
            }
        }
        __syncthreads();
    }
}

// ---------------- gc = mean over S of ln2 output ----------------
__global__ void __launch_bounds__(256) gc_mean_kernel(const float* __restrict__ in,
                                                      float* __restrict__ gc)
{
    __shared__ float smv[256];
    int b = blockIdx.y, dchunk = blockIdx.x, tid = threadIdx.x;
    int d = dchunk*128 + (tid & 127);
    int half = tid >> 7;
    float acc = 0.f;
    const float* base = in + ((size_t)b*Sq + half*1024)*Dq + d;
    for (int s = 0; s < 1024; ++s) acc += base[(size_t)s*Dq];
    smv[tid] = acc;
    __syncthreads();
    if (tid < 128) gc[b*Dq + d] = (smv[tid] + smv[tid+128]) * (1.0f/2048.0f);
}

// ---------------- tiny global MLP ----------------
__global__ void __launch_bounds__(256) global_mlp_kernel(
    const float* __restrict__ gc,
    const float* __restrict__ gw1, const float* __restrict__ gb1,
    const float* __restrict__ gw2, const float* __restrict__ gb2,
    const float* __restrict__ gw3, const float* __restrict__ gb3,
    float* __restrict__ gv)
{
    __shared__ float xs[1024], h1[512], h2[256], red[8];
    int b = blockIdx.x, tid = threadIdx.x, w = tid >> 5, l = tid & 31;
    for (int i = tid; i < 1024; i += 256) xs[i] = gc[b*Dq + i];
    __syncthreads();
    for (int o = w*64; o < w*64 + 64; ++o) {
        const float* wr = gw1 + (size_t)o*1024;
        float acc = 0.f;
        for (int k = l; k < 1024; k += 32) acc += xs[k]*__ldg(wr + k);
        #pragma unroll
        for (int off = 16; off; off >>= 1) acc += __shfl_xor_sync(0xffffffffu, acc, off);
        if (l == 0) h1[o] = gelu_f(acc + __ldg(gb1 + o));
    }
    __syncthreads();
    for (int o = w*32; o < w*32 + 32; ++o) {
        const float* wr = gw2 + (size_t)o*512;
        float acc = 0.f;
        for (int k = l; k < 512; k += 32) acc += h1[k]*__ldg(wr + k);
        #pragma unroll
        for (int off = 16; off; off >>= 1) acc += __shfl_xor_sync(0xffffffffu, acc, off);
        if (l == 0) h2[o] = gelu_f(acc + __ldg(gb2 + o));
    }
    __syncthreads();
    float acc = h2[tid & 255] * __ldg(gw3 + (tid & 255));
    #pragma unroll
    for (int off = 16; off; off >>= 1) acc += __shfl_xor_sync(0xffffffffu, acc, off);
    if (l == 0) red[w] = acc;
    __syncthreads();
    if (tid == 0) {
        float s = 0.f;
        #pragma unroll
        for (int i = 0; i < 8; i++) s += red[i];
        gv[b] = sigmoid_f(s + __ldg(gb3));
    }
}

// ---------------- tf head ----------------
__global__ void __launch_bounds__(256) tf_head_kernel(const float* __restrict__ c3,
                                                      const float* __restrict__ w4,
                                                      const float* __restrict__ b4,
                                                      float* __restrict__ tf)
{
    int tid = threadIdx.x, w = tid >> 5, l = tid & 31;
    int row = blockIdx.x*8 + w;
    const float* cr = c3 + (size_t)row*256;
    float acc = 0.f;
    #pragma unroll
    for (int k = l; k < 256; k += 32) acc += cr[k]*__ldg(w4 + k);
    #pragma unroll
    for (int off = 16; off; off >>= 1) acc += __shfl_xor_sync(0xffffffffu, acc, off);
    if (l == 0) tf[row] = sigmoid_f(acc + __ldg(b4));
}

// ---------------- mobius twist update ----------------
template<bool ADDRES>
__global__ void __launch_bounds__(256) mobius_kernel(
    const float* __restrict__ in, const float* __restrict__ tf,
    const float* __restrict__ gv, const float* __restrict__ ar,
    const float* __restrict__ res, float* __restrict__ outp)
{
    int row = blockIdx.x, tid = threadIdx.x;
    int b = row >> 11;
    float coup = 0.1f + __ldg(ar)*((0.7f*__ldg(gv + b) + 0.3f*__ldg(tf + row)) - 0.5f)*2.0f;
    const float4* ir = reinterpret_cast<const float4*>(in + (size_t)row*Dq);
    int j = tid*4;
    float sign = (j < 256 || j >= 768) ? 1.f : -1.f;
    int src4 = tid + ((j < 512) ? 128 : -128);
    float4 xv = ir[tid], tv = ir[src4];
    float cs = coup*sign;
    float4 o;
    o.x = xv.x + cs*tv.x; o.y = xv.y + cs*tv.y;
    o.z = xv.z + cs*tv.z; o.w = xv.w + cs*tv.w;
    if (ADDRES) {
        float4 rvv = reinterpret_cast<const float4*>(res + (size_t)row*Dq)[tid];
        o.x += rvv.x; o.y += rvv.y; o.z += rvv.z; o.w += rvv.w;
    }
    reinterpret_cast<float4*>(outp + (size_t)row*Dq)[tid] = o;
}

// ---------------- host driver ----------------
static float* symaddr(const void* sym) {
    void* p = nullptr;
    cudaGetSymbolAddress(&p, sym);
    return (float*)p;
}

extern "C" void kernel_launch(void* const* d_in, const int* in_sizes, int n_in,
                              void* d_out, int out_size) {
    const float* x     = (const float*)d_in[0];
    const float* g1w   = (const float*)d_in[1];
    const float* g1b   = (const float*)d_in[2];
    const float* g2w   = (const float*)d_in[3];
    const float* g2b   = (const float*)d_in[4];
    const float* W_ih0 = (const float*)d_in[5];
    const float* W_hh0 = (const float*)d_in[6];
    const float* b_ih0 = (const float*)d_in[7];
    const float* b_hh0 = (const float*)d_in[8];
    const float* W_ih1 = (const float*)d_in[9];
    const float* W_hh1 = (const float*)d_in[10];
    const float* b_ih1 = (const float*)d_in[11];
    const float* b_hh1 = (const float*)d_in[12];
    const float* cw1   = (const float*)d_in[13];
    const float* cb1   = (const float*)d_in[14];
    const float* cw2   = (const float*)d_in[15];
    const float* cb2   = (const float*)d_in[16];
    const float* cw3   = (const float*)d_in[17];
    const float* cb3   = (const float*)d_in[18];
    const float* cw4   = (const float*)d_in[19];
    const float* cb4   = (const float*)d_in[20];
    const float* gw1   = (const float*)d_in[21];
    const float* gb1   = (const float*)d_in[22];
    const float* gw2   = (const float*)d_in[23];
    const float* gb2   = (const float*)d_in[24];
    const float* gw3   = (const float*)d_in[25];
    const float* gb3   = (const float*)d_in[26];
    const float* arng  = (const float*)d_in[27];
    const float* fw1   = (const float*)d_in[28];
    const float* fb1   = (const float*)d_in[29];
    const float* fw2   = (const float*)d_in[30];
    const float* fb2   = (const float*)d_in[31];
    float* out = (float*)d_out;

    float* p_ln   = symaddr(g_ln);
    float* p_xi   = symaddr(g_xi);
    float* p_x1   = symaddr(g_x1);
    float* p_mobA = symaddr(g_mobA);
    float* p_mobB = symaddr(g_mobB);
    float* p_c1   = symaddr(g_c1);
    float* p_c2   = symaddr(g_c2);
    float* p_c3   = symaddr(g_c3);
    float* p_tf   = symaddr(g_tf);
    float* p_ffn  = symaddr(g_ffn);
    float* p_gc   = symaddr(g_gc);
    float* p_gv   = symaddr(g_gv);

    cudaFuncSetAttribute(gru_kernel, cudaFuncAttributeMaxDynamicSharedMemorySize,
                         GRU_SMEM_BYTES);

    // Block 1: ln1 -> GRU0 -> GRU1 -> + x
    ln_kernel<<<Mrows, 256>>>(x, g1w, g1b, p_ln);
    tgemm_kernel<0,false><<<dim3(3072/128, Mrows/128), 256>>>(
        p_ln, W_ih0, b_ih0, nullptr, p_xi, Mrows, 3072, 1024);
    gru_kernel<<<GRU_BLOCKS, 256, GRU_SMEM_BYTES>>>(p_xi, W_hh0, b_hh0, nullptr, p_ln);
    tgemm_kernel<0,false><<<dim3(3072/128, Mrows/128), 256>>>(
        p_ln, W_ih1, b_ih1, nullptr, p_xi, Mrows, 3072, 1024);
    gru_kernel<<<GRU_BLOCKS, 256, GRU_SMEM_BYTES>>>(p_xi, W_hh1, b_hh1, x, p_x1);

    // Block 2: ln2 -> adaptive mobius -> + x1
    ln_kernel<<<Mrows, 256>>>(p_x1, g2w, g2b, p_mobA);
    gc_mean_kernel<<<dim3(8, 4), 256>>>(p_mobA, p_gc);
    global_mlp_kernel<<<4, 256>>>(p_gc, gw1, gb1, gw2, gb2, gw3, gb3, p_gv);

    float* cin = p_mobA;
    float* cout = p_mobB;
    for (int cyc = 0; cyc < 3; ++cyc) {
        tgemm_kernel<1,false><<<dim3(1024/128, Mrows/128), 256>>>(
            cin, cw1, cb1, nullptr, p_c1, Mrows, 1024, 1024);
        tgemm_kernel<1,false><<<dim3(512/128, Mrows/128), 256>>>(
            p_c1, cw2, cb2, nullptr, p_c2, Mrows, 512, 1024);
        tgemm_kernel<1,false><<<dim3(256/128, Mrows/128), 256>>>(
            p_c2, cw3, cb3, nullptr, p_c3, Mrows, 256, 512);
        tf_head_kernel<<<Mrows/8, 256>>>(p_c3, cw4, cb4, p_tf);
        if (cyc == 2) {
            mobius_kernel<true><<<Mrows, 256>>>(cin, p_tf, p_gv, arng, p_x1, cout);
        } else {
            mobius_kernel<false><<<Mrows, 256>>>(cin, p_tf, p_gv, arng, nullptr, cout);
        }
        float* tmp = cin; cin = cout; cout = tmp;
    }
    float* p_x2 = p_mobB;

    // Block 3: FFN residual
    tgemm_kernel<1,false><<<dim3(4096/128, Mrows/128), 256>>>(
        p_x2, fw1, fb1, nullptr, p_ffn, Mrows, 4096, 1024);
    tgemm_kernel<0,true><<<dim3(1024/128, Mrows/128), 256>>>(
        p_ffn, fw2, fb2, p_x2, out, Mrows, 1024, 4096);

    (void)in_sizes; (void)n_in; (void)out_size;
}

// round 16
// speedup vs baseline: 1.7602x; 1.5026x over previous
#include <cuda_runtime.h>
#include <math.h>
#include <stdint.h>

#define Bq 4
#define Sq 2048
#define Dq 1024
#define Mrows (Bq*Sq)   // 8192
#define GRU_BLOCKS 128

// ---------------- static device scratch (zero-initialized at load) ----------------
__device__ float g_ln [Mrows*Dq];
__device__ float g_xi [Mrows*3*Dq];
__device__ float g_x1 [Mrows*Dq];
__device__ float g_mobA[Mrows*Dq];
__device__ float g_mobB[Mrows*Dq];
__device__ float g_c1 [Mrows*Dq];
__device__ float g_c2 [Mrows*(Dq/2)];
__device__ float g_c3 [Mrows*(Dq/4)];
__device__ float g_tf [Mrows];
__device__ float g_ffn[Mrows*4*Dq];
__device__ float g_gc [Bq*Dq];
__device__ float g_gv [Bq];
__device__ float g_hbuf[2*Bq*Dq];
__device__ int           g_bar_count;   // proven-good R7 barrier state
__device__ volatile int  g_bar_sense;

// ---------------- helpers ----------------
__device__ __forceinline__ float gelu_f(float x) {
    return 0.5f * x * (1.0f + erff(x * 0.70710678118654752f));
}
__device__ __forceinline__ float sigmoid_f(float x) {
    return 1.0f / (1.0f + expf(-x));
}
__device__ __forceinline__ uint32_t f2tf32(float f) {
    uint32_t u;
    asm("cvt.rna.tf32.f32 %0, %1;" : "=r"(u) : "f"(f));
    return u;
}
__device__ __forceinline__ void mma8(float* d, const uint32_t* a, const uint32_t* b) {
    asm volatile(
        "mma.sync.aligned.m16n8k8.row.col.f32.tf32.tf32.f32 "
        "{%0,%1,%2,%3}, {%4,%5,%6,%7}, {%8,%9}, {%0,%1,%2,%3};"
        : "+f"(d[0]), "+f"(d[1]), "+f"(d[2]), "+f"(d[3])
        : "r"(a[0]), "r"(a[1]), "r"(a[2]), "r"(a[3]), "r"(b[0]), "r"(b[1]));
}

// ---------------- LayerNorm: one block per row ----------------
__global__ void __launch_bounds__(256) ln_kernel(const float* __restrict__ x,
                                                 const float* __restrict__ gw,
                                                 const float* __restrict__ gb,
                                                 float* __restrict__ y)
{
    __shared__ float redA[8], redB[8];
    __shared__ float s_mean, s_rstd;
    int row = blockIdx.x, tid = threadIdx.x;
    const float4* xr = reinterpret_cast<const float4*>(x + (size_t)row*Dq);
    float4 v = xr[tid];
    float s = v.x+v.y+v.z+v.w;
    float q = v.x*v.x+v.y*v.y+v.z*v.z+v.w*v.w;
    #pragma unroll
    for (int o = 16; o > 0; o >>= 1) {
        s += __shfl_xor_sync(0xffffffffu, s, o);
        q += __shfl_xor_sync(0xffffffffu, q, o);
    }
    if ((tid & 31) == 0) { redA[tid>>5] = s; redB[tid>>5] = q; }
    __syncthreads();
    if (tid == 0) {
        float ss = 0.f, qq = 0.f;
        #pragma unroll
        for (int i = 0; i < 8; i++) { ss += redA[i]; qq += redB[i]; }
        float m = ss * (1.0f/1024.0f);
        float var = qq * (1.0f/1024.0f) - m*m;
        s_mean = m; s_rstd = rsqrtf(var + 1e-5f);
    }
    __syncthreads();
    float m = s_mean, r = s_rstd;
    const float4* g4 = reinterpret_cast<const float4*>(gw);
    const float4* b4 = reinterpret_cast<const float4*>(gb);
    float4 gv = g4[tid], bv = b4[tid], o;
    o.x = (v.x - m)*r*gv.x + bv.x;
    o.y = (v.y - m)*r*gv.y + bv.y;
    o.z = (v.z - m)*r*gv.z + bv.z;
    o.w = (v.w - m)*r*gv.w + bv.w;
    reinterpret_cast<float4*>(y + (size_t)row*Dq)[tid] = o;
}

// ---------------- tf32 tensor-core GEMM (unchanged from passing R14) ----------------
template<int ACT, bool RES>
__global__ void __launch_bounds__(256) tgemm_kernel(
    const float* __restrict__ A, const float* __restrict__ W,
    const float* __restrict__ bias, const float* __restrict__ res,
    float* __restrict__ C, int M, int N, int K)
{
    __shared__ uint32_t As[128*36];
    __shared__ uint32_t Ws[128*36];
    const int tid = threadIdx.x;
    const int lane = tid & 31, wid = tid >> 5;
    const int g = lane >> 2, tig = lane & 3;
    const int wm = wid >> 2, wn = wid & 3;
    const int row0 = blockIdx.y * 128, col0 = blockIdx.x * 128;
    const int Kq = K >> 2;

    float acc[4][4][4];
    #pragma unroll
    for (int i = 0; i < 4; i++)
        #pragma unroll
        for (int j = 0; j < 4; j++)
            #pragma unroll
            for (int e = 0; e < 4; e++) acc[i][j][e] = 0.f;

    const float4* Ag = reinterpret_cast<const float4*>(A) + (size_t)row0 * Kq;
    const float4* Wg = reinterpret_cast<const float4*>(W) + (size_t)col0 * Kq;

    int fm[4], fq[4];
    #pragma unroll
    for (int i = 0; i < 4; i++) { int f = tid + i*256; fm[i] = f >> 3; fq[i] = f & 7; }

    float4 pa[4], pw[4];
    #pragma unroll
    for (int i = 0; i < 4; i++) {
        pa[i] = Ag[(size_t)fm[i]*Kq + fq[i]];
        pw[i] = Wg[(size_t)fm[i]*Kq + fq[i]];
    }

    for (int k0 = 0; k0 < K; k0 += 32) {
        __syncthreads();
        #pragma unroll
        for (int i = 0; i < 4; i++) {
            uint4 ua, uw;
            ua.x = f2tf32(pa[i].x); ua.y = f2tf32(pa[i].y);
            ua.z = f2tf32(pa[i].z); ua.w = f2tf32(pa[i].w);
            uw.x = f2tf32(pw[i].x); uw.y = f2tf32(pw[i].y);
            uw.z = f2tf32(pw[i].z); uw.w = f2tf32(pw[i].w);
            *reinterpret_cast<uint4*>(&As[fm[i]*36 + fq[i]*4]) = ua;
            *reinterpret_cast<uint4*>(&Ws[fm[i]*36 + fq[i]*4]) = uw;
        }
        __syncthreads();
        if (k0 + 32 < K) {
            int kb4 = (k0 + 32) >> 2;
            #pragma unroll
            for (int i = 0; i < 4; i++) {
                pa[i] = Ag[(size_t)fm[i]*Kq + kb4 + fq[i]];
                pw[i] = Wg[(size_t)fm[i]*Kq + kb4 + fq[i]];
            }
        }
        #pragma unroll
        for (int ks = 0; ks < 4; ++ks) {
            int kb = ks * 8;
            uint32_t af[4][4];
            #pragma unroll
            for (int mt = 0; mt < 4; ++mt) {
                int mr = wm*64 + mt*16;
                af[mt][0] = As[(mr + g    )*36 + kb + tig    ];
                af[mt][1] = As[(mr + g + 8)*36 + kb + tig    ];
                af[mt][2] = As[(mr + g    )*36 + kb + tig + 4];
                af[mt][3] = As[(mr + g + 8)*36 + kb + tig + 4];
            }
            uint32_t bf[4][2];
            #pragma unroll
            for (int nt = 0; nt < 4; ++nt) {
                int nc = wn*32 + nt*8;
                bf[nt][0] = Ws[(nc + g)*36 + kb + tig    ];
                bf[nt][1] = Ws[(nc + g)*36 + kb + tig + 4];
            }
            #pragma unroll
            for (int mt = 0; mt < 4; ++mt)
                #pragma unroll
                for (int nt = 0; nt < 4; ++nt)
                    mma8(acc[mt][nt], af[mt], bf[nt]);
        }
    }

    #pragma unroll
    for (int mt = 0; mt < 4; ++mt) {
        #pragma unroll
        for (int nt = 0; nt < 4; ++nt) {
            int ra = row0 + wm*64 + mt*16 + g;
            int cc = col0 + wn*32 + nt*8 + 2*tig;
            float b0 = __ldg(bias + cc), b1 = __ldg(bias + cc + 1);
            #pragma unroll
            for (int h = 0; h < 2; ++h) {
                int r = ra + h*8;
                float v0 = acc[mt][nt][h*2+0] + b0;
                float v1 = acc[mt][nt][h*2+1] + b1;
                if (ACT == 1) { v0 = gelu_f(v0); v1 = gelu_f(v1); }
                else if (ACT == 2) { v0 = sigmoid_f(v0); v1 = sigmoid_f(v1); }
                if (RES) {
                    float2 rv = *reinterpret_cast<const float2*>(res + (size_t)r*N + cc);
                    v0 += rv.x; v1 += rv.y;
                }
                float2 o; o.x = v0; o.y = v1;
                *reinterpret_cast<float2*>(C + (size_t)r*N + cc) = o;
            }
        }
    }
}

// ---------------- persistent GRU layer: W_hh in REGISTERS, h in smem ----------------
// Warp w owns local rows 3w..3w+2 (lr = gate*8 + unit); lane l owns k in [32l, 32l+32).
// h staged to smem with XOR swizzle slot(b,l,k4) = b*264 + l*8 + (k4 ^ (l&7)) -> LDS
// phases conflict-free. Barrier semantics identical to the proven R7 kernel.
__global__ void __launch_bounds__(256,1) gru_kernel(
    const float* __restrict__ xi, const float* __restrict__ Whh,
    const float* __restrict__ bhh, const float* __restrict__ res,
    float* __restrict__ out)
{
    __shared__ float4 hs4[4*264];
    __shared__ float  hh_s[96];
    const float* hsF = reinterpret_cast<const float*>(hs4);

    const int tid = threadIdx.x;
    const int u0  = blockIdx.x * 8;
    const int w   = tid >> 5, l = tid & 31;

    // persistent W load (once; reused 2048 steps)
    float4 Wr[3][8];
    #pragma unroll
    for (int r = 0; r < 3; ++r) {
        int lr = 3*w + r;
        int gg = lr >> 3, ui = lr & 7;
        const float4* src = reinterpret_cast<const float4*>(
            Whh + (size_t)(gg*1024 + u0 + ui)*1024 + l*32);
        #pragma unroll
        for (int k4 = 0; k4 < 8; ++k4) Wr[r][k4] = __ldg(src + k4);
    }

    float b_r = 0.f, b_z = 0.f, b_n = 0.f;
    const int p2i = tid >> 2, p2b = tid & 3;   // valid when tid < 32
    if (tid < 32) {
        b_r = __ldg(bhh + u0 + p2i);
        b_z = __ldg(bhh + 1024 + u0 + p2i);
        b_n = __ldg(bhh + 2048 + u0 + p2i);
    }

    int local_sense = 0;
    for (int t = 0; t < Sq; ++t) {
        // stage h_{t-1} into swizzled smem
        if (t == 0) {
            float4 z4 = make_float4(0.f,0.f,0.f,0.f);
            for (int s = tid; s < 4*264; s += 256) hs4[s] = z4;
        } else {
            int rb = t & 1;
            #pragma unroll
            for (int i = 0; i < 4; ++i) {
                int s = tid + i*256;              // 0..1023
                int b = s >> 8, rem = s & 255;
                int ll = rem >> 3, k4 = rem & 7;
                const float4* gp = reinterpret_cast<const float4*>(
                    g_hbuf + rb*4096 + b*1024 + ll*32) + k4;
                hs4[b*264 + ll*8 + (k4 ^ (ll & 7))] = __ldcg(gp);
            }
        }
        float xr=0.f, xz=0.f, xn=0.f, rv=0.f;
        if (tid < 32) {
            size_t rowb = (size_t)p2b*Sq + t;
            const float* xrow = xi + rowb*3072;
            xr = __ldg(xrow + u0 + p2i);
            xz = __ldg(xrow + 1024 + u0 + p2i);
            xn = __ldg(xrow + 2048 + u0 + p2i);
            if (res) rv = __ldg(res + rowb*1024 + u0 + p2i);
        }
        __syncthreads();

        // dot phase: per-lane partial sums over own k-range, all from registers+swizzled LDS
        float acc[3][4];
        #pragma unroll
        for (int r = 0; r < 3; ++r)
            #pragma unroll
            for (int b = 0; b < 4; ++b) acc[r][b] = 0.f;
        #pragma unroll
        for (int b = 0; b < 4; ++b) {
            #pragma unroll
            for (int k4 = 0; k4 < 8; ++k4) {
                float4 hv = hs4[b*264 + l*8 + (k4 ^ (l & 7))];
                #pragma unroll
                for (int r = 0; r < 3; ++r) {
                    float4 wv = Wr[r][k4];
                    acc[r][b] += hv.x*wv.x + hv.y*wv.y + hv.z*wv.z + hv.w*wv.w;
                }
            }
        }
        #pragma unroll
        for (int off = 16; off; off >>= 1)
            #pragma unroll
            for (int r = 0; r < 3; ++r)
                #pragma unroll
                for (int b = 0; b < 4; ++b)
                    acc[r][b] += __shfl_xor_sync(0xffffffffu, acc[r][b], off);
        if (l == 0) {
            #pragma unroll
            for (int r = 0; r < 3; ++r)
                #pragma unroll
                for (int b = 0; b < 4; ++b)
                    hh_s[(3*w + r)*4 + b] = acc[r][b];
        }
        __syncthreads();

        if (tid < 32) {
            float hr = hh_s[(0*8 + p2i)*4 + p2b] + b_r;
            float hz = hh_s[(1*8 + p2i)*4 + p2b] + b_z;
            float hn = hh_s[(2*8 + p2i)*4 + p2b] + b_n;
            int k = u0 + p2i;
            int ll = k >> 5, kk4 = (k >> 2) & 7, e = k & 3;
            float hprev = hsF[(p2b*264 + ll*8 + (kk4 ^ (ll & 7)))*4 + e];
            float rg = sigmoid_f(xr + hr);
            float zg = sigmoid_f(xz + hz);
            float ng = tanhf(xn + rg*hn);
            float hnew = (1.f - zg)*ng + zg*hprev;
            int wb = (t + 1) & 1;
            __stcg(g_hbuf + wb*4096 + p2b*1024 + k, hnew);
            out[((size_t)p2b*Sq + t)*1024 + k] = hnew + rv;
            __threadfence();
        }
        __syncthreads();

        // grid barrier (R7 proven: atomic count + volatile sense; even count per
        // launch so state returns to 0 -> graph-replay safe)
        local_sense ^= 1;
        if (tid == 0) {
            int arrived = atomicAdd(&g_bar_count, 1);
            if (arrived == (int)gridDim.x - 1) {
                g_bar_count = 0;
                __threadfence();
                g_bar_sense = local_sense;
            } else {
                while (g_bar_sense != local_sense) { }
                __threadfence();
            }
        }
        __syncthreads();
    }
}

// ---------------- gc = mean over S of ln2 output ----------------
__global__ void __launch_bounds__(256) gc_mean_kernel(const float* __restrict__ in,
                                                      float* __restrict__ gc)
{
    __shared__ float smv[256];
    int b = blockIdx.y, dchunk = blockIdx.x, tid = threadIdx.x;
    int d = dchunk*128 + (tid & 127);
    int half = tid >> 7;
    float acc = 0.f;
    const float* base = in + ((size_t)b*Sq + half*1024)*Dq + d;
    for (int s = 0; s < 1024; ++s) acc += base[(size_t)s*Dq];
    smv[tid] = acc;
    __syncthreads();
    if (tid < 128) gc[b*Dq + d] = (smv[tid] + smv[tid+128]) * (1.0f/2048.0f);
}

// ---------------- tiny global MLP ----------------
__global__ void __launch_bounds__(256) global_mlp_kernel(
    const float* __restrict__ gc,
    const float* __restrict__ gw1, const float* __restrict__ gb1,
    const float* __restrict__ gw2, const float* __restrict__ gb2,
    const float* __restrict__ gw3, const float* __restrict__ gb3,
    float* __restrict__ gv)
{
    __shared__ float xs[1024], h1[512], h2[256], red[8];
    int b = blockIdx.x, tid = threadIdx.x, w = tid >> 5, l = tid & 31;
    for (int i = tid; i < 1024; i += 256) xs[i] = gc[b*Dq + i];
    __syncthreads();
    for (int o = w*64; o < w*64 + 64; ++o) {
        const float* wr = gw1 + (size_t)o*1024;
        float acc = 0.f;
        for (int k = l; k < 1024; k += 32) acc += xs[k]*__ldg(wr + k);
        #pragma unroll
        for (int off = 16; off; off >>= 1) acc += __shfl_xor_sync(0xffffffffu, acc, off);
        if (l == 0) h1[o] = gelu_f(acc + __ldg(gb1 + o));
    }
    __syncthreads();
    for (int o = w*32; o < w*32 + 32; ++o) {
        const float* wr = gw2 + (size_t)o*512;
        float acc = 0.f;
        for (int k = l; k < 512; k += 32) acc += h1[k]*__ldg(wr + k);
        #pragma unroll
        for (int off = 16; off; off >>= 1) acc += __shfl_xor_sync(0xffffffffu, acc, off);
        if (l == 0) h2[o] = gelu_f(acc + __ldg(gb2 + o));
    }
    __syncthreads();
    float acc = h2[tid & 255] * __ldg(gw3 + (tid & 255));
    #pragma unroll
    for (int off = 16; off; off >>= 1) acc += __shfl_xor_sync(0xffffffffu, acc, off);
    if (l == 0) red[w] = acc;
    __syncthreads();
    if (tid == 0) {
        float s = 0.f;
        #pragma unroll
        for (int i = 0; i < 8; i++) s += red[i];
        gv[b] = sigmoid_f(s + __ldg(gb3));
    }
}

// ---------------- tf head ----------------
__global__ void __launch_bounds__(256) tf_head_kernel(const float* __restrict__ c3,
                                                      const float* __restrict__ w4,
                                                      const float* __restrict__ b4,
                                                      float* __restrict__ tf)
{
    int tid = threadIdx.x, w = tid >> 5, l = tid & 31;
    int row = blockIdx.x*8 + w;
    const float* cr = c3 + (size_t)row*256;
    float acc = 0.f;
    #pragma unroll
    for (int k = l; k < 256; k += 32) acc += cr[k]*__ldg(w4 + k);
    #pragma unroll
    for (int off = 16; off; off >>= 1) acc += __shfl_xor_sync(0xffffffffu, acc, off);
    if (l == 0) tf[row] = sigmoid_f(acc + __ldg(b4));
}

// ---------------- mobius twist update ----------------
template<bool ADDRES>
__global__ void __launch_bounds__(256) mobius_kernel(
    const float* __restrict__ in, const float* __restrict__ tf,
    const float* __restrict__ gv, const float* __restrict__ ar,
    const float* __restrict__ res, float* __restrict__ outp)
{
    int row = blockIdx.x, tid = threadIdx.x;
    int b = row >> 11;
    float coup = 0.1f + __ldg(ar)*((0.7f*__ldg(gv + b) + 0.3f*__ldg(tf + row)) - 0.5f)*2.0f;
    const float4* ir = reinterpret_cast<const float4*>(in + (size_t)row*Dq);
    int j = tid*4;
    float sign = (j < 256 || j >= 768) ? 1.f : -1.f;
    int src4 = tid + ((j < 512) ? 128 : -128);
    float4 xv = ir[tid], tv = ir[src4];
    float cs = coup*sign;
    float4 o;
    o.x = xv.x + cs*tv.x; o.y = xv.y + cs*tv.y;
    o.z = xv.z + cs*tv.z; o.w = xv.w + cs*tv.w;
    if (ADDRES) {
        float4 rvv = reinterpret_cast<const float4*>(res + (size_t)row*Dq)[tid];
        o.x += rvv.x; o.y += rvv.y; o.z += rvv.z; o.w += rvv.w;
    }
    reinterpret_cast<float4*>(outp + (size_t)row*Dq)[tid] = o;
}

// ---------------- host driver ----------------
static float* symaddr(const void* sym) {
    void* p = nullptr;
    cudaGetSymbolAddress(&p, sym);
    return (float*)p;
}

extern "C" void kernel_launch(void* const* d_in, const int* in_sizes, int n_in,
                              void* d_out, int out_size) {
    const float* x     = (const float*)d_in[0];
    const float* g1w   = (const float*)d_in[1];
    const float* g1b   = (const float*)d_in[2];
    const float* g2w   = (const float*)d_in[3];
    const float* g2b   = (const float*)d_in[4];
    const float* W_ih0 = (const float*)d_in[5];
    const float* W_hh0 = (const float*)d_in[6];
    const float* b_ih0 = (const float*)d_in[7];
    const float* b_hh0 = (const float*)d_in[8];
    const float* W_ih1 = (const float*)d_in[9];
    const float* W_hh1 = (const float*)d_in[10];
    const float* b_ih1 = (const float*)d_in[11];
    const float* b_hh1 = (const float*)d_in[12];
    const float* cw1   = (const float*)d_in[13];
    const float* cb1   = (const float*)d_in[14];
    const float* cw2   = (const float*)d_in[15];
    const float* cb2   = (const float*)d_in[16];
    const float* cw3   = (const float*)d_in[17];
    const float* cb3   = (const float*)d_in[18];
    const float* cw4   = (const float*)d_in[19];
    const float* cb4   = (const float*)d_in[20];
    const float* gw1   = (const float*)d_in[21];
    const float* gb1   = (const float*)d_in[22];
    const float* gw2   = (const float*)d_in[23];
    const float* gb2   = (const float*)d_in[24];
    const float* gw3   = (const float*)d_in[25];
    const float* gb3   = (const float*)d_in[26];
    const float* arng  = (const float*)d_in[27];
    const float* fw1   = (const float*)d_in[28];
    const float* fb1   = (const float*)d_in[29];
    const float* fw2   = (const float*)d_in[30];
    const float* fb2   = (const float*)d_in[31];
    float* out = (float*)d_out;

    float* p_ln   = symaddr(g_ln);
    float* p_xi   = symaddr(g_xi);
    float* p_x1   = symaddr(g_x1);
    float* p_mobA = symaddr(g_mobA);
    float* p_mobB = symaddr(g_mobB);
    float* p_c1   = symaddr(g_c1);
    float* p_c2   = symaddr(g_c2);
    float* p_c3   = symaddr(g_c3);
    float* p_tf   = symaddr(g_tf);
    float* p_ffn  = symaddr(g_ffn);
    float* p_gc   = symaddr(g_gc);
    float* p_gv   = symaddr(g_gv);

    // Block 1: ln1 -> GRU0 -> GRU1 -> + x
    ln_kernel<<<Mrows, 256>>>(x, g1w, g1b, p_ln);
    tgemm_kernel<0,false><<<dim3(3072/128, Mrows/128), 256>>>(
        p_ln, W_ih0, b_ih0, nullptr, p_xi, Mrows, 3072, 1024);
    gru_kernel<<<GRU_BLOCKS, 256>>>(p_xi, W_hh0, b_hh0, nullptr, p_ln);
    tgemm_kernel<0,false><<<dim3(3072/128, Mrows/128), 256>>>(
        p_ln, W_ih1, b_ih1, nullptr, p_xi, Mrows, 3072, 1024);
    gru_kernel<<<GRU_BLOCKS, 256>>>(p_xi, W_hh1, b_hh1, x, p_x1);

    // Block 2: ln2 -> adaptive mobius -> + x1
    ln_kernel<<<Mrows, 256>>>(p_x1, g2w, g2b, p_mobA);
    gc_mean_kernel<<<dim3(8, 4), 256>>>(p_mobA, p_gc);
    global_mlp_kernel<<<4, 256>>>(p_gc, gw1, gb1, gw2, gb2, gw3, gb3, p_gv);

    float* cin = p_mobA;
    float* cout = p_mobB;
    for (int cyc = 0; cyc < 3; ++cyc) {
        tgemm_kernel<1,false><<<dim3(1024/128, Mrows/128), 256>>>(
            cin, cw1, cb1, nullptr, p_c1, Mrows, 1024, 1024);
        tgemm_kernel<1,false><<<dim3(512/128, Mrows/128), 256>>>(
            p_c1, cw2, cb2, nullptr, p_c2, Mrows, 512, 1024);
        tgemm_kernel<1,false><<<dim3(256/128, Mrows/128), 256>>>(
            p_c2, cw3, cb3, nullptr, p_c3, Mrows, 256, 512);
        tf_head_kernel<<<Mrows/8, 256>>>(p_c3, cw4, cb4, p_tf);
        if (cyc == 2) {
            mobius_kernel<true><<<Mrows, 256>>>(cin, p_tf, p_gv, arng, p_x1, cout);
        } else {
            mobius_kernel<false><<<Mrows, 256>>>(cin, p_tf, p_gv, arng, nullptr, cout);
        }
        float* tmp = cin; cin = cout; cout = tmp;
    }
    float* p_x2 = p_mobB;

    // Block 3: FFN residual
    tgemm_kernel<1,false><<<dim3(4096/128, Mrows/128), 256>>>(
        p_x2, fw1, fb1, nullptr, p_ffn, Mrows, 4096, 1024);
    tgemm_kernel<0,true><<<dim3(1024/128, Mrows/128), 256>>>(
        p_ffn, fw2, fb2, p_x2, out, Mrows, 1024, 4096);

    (void)in_sizes; (void)n_in; (void)out_size;
}